// round 5
// baseline (speedup 1.0000x reference)
#include <cuda_runtime.h>
#include <cuda_fp16.h>
#include <math.h>
#include <stdint.h>

// Problem constants
#define Bn 2
#define Sn 1024
#define Dn 1024
#define NHn 16
#define HDn 64
#define En 8
#define HIDn 4096
#define Tn (Bn*Sn)          // 2048 tokens
#define MAXROWS 5248        // >= 4096 assignments + 8*127 padding, mult of 128

// ---------------- scratch (static device globals; no allocation) -------------
static __device__ __half g_XNh [Tn*Dn];
static __device__ float  g_Qb  [Tn*Dn];
static __device__ float  g_Kb  [Tn*Dn];
static __device__ float  g_Vb  [Tn*Dn];
static __device__ __half g_ATTh[Tn*Dn];
static __device__ float  g_Hb  [Tn*Dn];
static __device__ float  g_XN2 [Tn*Dn];
static __device__ __half g_XN2h[Tn*Dn];
static __device__ float  g_GBUF[(size_t)MAXROWS*HIDn];
static __device__ float  g_UBUF[(size_t)MAXROWS*HIDn];
static __device__ __half g_Hh  [(size_t)MAXROWS*HIDn];
// routing
static __device__ int   g_cnt[En];
static __device__ int   g_cursor[En];
static __device__ int   g_rowtok[MAXROWS];
static __device__ int   g_rowexp[MAXROWS];
static __device__ float g_rowgate[MAXROWS];
static __device__ int   g_totalrows;
static __device__ float g_gsum[En];
static __device__ float g_psum[En];
static __device__ int   g_expid[Tn*2];
static __device__ float g_gateval[Tn*2];

// ======================= PTX helpers =========================================
static __device__ __forceinline__ uint32_t smem_u32_(const void* p){
    uint32_t a;
    asm("{ .reg .u64 t; cvta.to.shared.u64 t, %1; cvt.u32.u64 %0, t; }"
        : "=r"(a) : "l"(p));
    return a;
}

#define LDSM_X4(r0,r1,r2,r3,addr) \
    asm volatile("ldmatrix.sync.aligned.m8n8.x4.shared.b16 {%0,%1,%2,%3}, [%4];" \
        : "=r"(r0),"=r"(r1),"=r"(r2),"=r"(r3) : "r"(addr))

#define MMA16816(c,a,b) \
    asm volatile("mma.sync.aligned.m16n8k16.row.col.f32.f16.f16.f32 " \
        "{%0,%1,%2,%3}, {%4,%5,%6,%7}, {%8,%9}, {%0,%1,%2,%3};" \
        : "+f"((c)[0]),"+f"((c)[1]),"+f"((c)[2]),"+f"((c)[3]) \
        : "r"((a)[0]),"r"((a)[1]),"r"((a)[2]),"r"((a)[3]), \
          "r"((b)[0]),"r"((b)[1]))

#define CP_COMMIT() asm volatile("cp.async.commit_group;" ::: "memory")
#define CP_WAIT0()  asm volatile("cp.async.wait_group 0;" ::: "memory")

static __device__ __forceinline__ void cp16_(uint32_t dst, const void* src, int srcsize){
    asm volatile("cp.async.cg.shared.global [%0], [%1], 16, %2;"
        :: "r"(dst), "l"((unsigned long long)__cvta_generic_to_global(src)),
           "r"(srcsize) : "memory");
}

// ============================== small kernels ================================
__global__ void k_reset() {
    int i = threadIdx.x;
    if (i < En) { g_cnt[i] = 0; g_gsum[i] = 0.f; g_psum[i] = 0.f; }
}

__global__ void k_rmsnorm(const float* __restrict__ x, const float* __restrict__ w,
                          float* __restrict__ y, __half* __restrict__ yh) {
    int t = blockIdx.x;
    const float* xr = x + (size_t)t * Dn;
    int base = threadIdx.x * 4;
    float4 xv = *(const float4*)(xr + base);
    float ss = xv.x*xv.x + xv.y*xv.y + xv.z*xv.z + xv.w*xv.w;
    #pragma unroll
    for (int o = 16; o; o >>= 1) ss += __shfl_xor_sync(0xffffffffu, ss, o);
    __shared__ float ws[8];
    if ((threadIdx.x & 31) == 0) ws[threadIdx.x >> 5] = ss;
    __syncthreads();
    float tot = ws[0]+ws[1]+ws[2]+ws[3]+ws[4]+ws[5]+ws[6]+ws[7];
    float sc = rsqrtf(tot * (1.f/(float)Dn) + 1e-6f);
    float4 wv = *(const float4*)(w + base);
    float4 o4;
    o4.x = wv.x*xv.x*sc; o4.y = wv.y*xv.y*sc;
    o4.z = wv.z*xv.z*sc; o4.w = wv.w*xv.w*sc;
    if (y) *(float4*)(y + (size_t)t*Dn + base) = o4;
    __half2 h0 = __floats2half2_rn(o4.x, o4.y);
    __half2 h1 = __floats2half2_rn(o4.z, o4.w);
    uint2 ho;
    ho.x = *reinterpret_cast<uint32_t*>(&h0);
    ho.y = *reinterpret_cast<uint32_t*>(&h1);
    *(uint2*)(yh + (size_t)t*Dn + base) = ho;
}

// ===================== mma.sync GEMM (HMMA tensor path) ======================
// C[128*mt.., 128*nt..] = A(fp16,lda) @ B(fp32,ldb)^T, fp32 accum.
// Tile 128x128x64. A: 2-stage cp.async. B: fp32 register prefetch -> cvt -> STS.
// One __syncthreads per K-stage.
#define EPI_PLAIN 0
#define EPI_RESID 1
#define EPI_DOWN  2
#define GEMM_SMEM (2*32768)

template<int NITER, int EPI, bool GATHER, bool ESEL>
__global__ __launch_bounds__(256, 2)
void k_gemm(const __half* __restrict__ A0, int lda,
            const float* __restrict__ B0, const float* __restrict__ B1,
            const float* __restrict__ B2,
            long bstride, int ldb,
            float* __restrict__ C0, float* __restrict__ C1c, float* __restrict__ C2c,
            int ldc,
            const float* __restrict__ resid, float* __restrict__ Cdual)
{
    int mt = blockIdx.y, nt = blockIdx.x;
    if (ESEL && mt*128 >= g_totalrows) return;
    const float* Bw = (blockIdx.z==0) ? B0 : ((blockIdx.z==1) ? B1 : B2);
    float* C = (blockIdx.z==0) ? C0 : ((blockIdx.z==1) ? C1c : C2c);
    if (ESEL) Bw += (long)g_rowexp[mt*128] * bstride;

    extern __shared__ __align__(128) char sm_[];
    uint32_t sbase = smem_u32_(sm_);

    int tid = threadIdx.x, lane = tid & 31, wid = tid >> 5;
    int warp_m = wid & 3, warp_n = wid >> 2;

    // staging: row = tid/2 (128 rows), each thread owns 4 16B fp16 chunks
    int lrow = tid >> 1;
    int lc0  = (tid & 1) * 4;
    const __half* asrc;
    bool avalid = true;
    if (GATHER){
        int tok = g_rowtok[mt*128 + lrow];
        avalid = (tok >= 0);
        asrc = A0 + (avalid ? (size_t)tok * lda : 0);
    } else {
        asrc = A0 + (size_t)(mt*128 + lrow) * lda;
    }
    const float* bsrc = Bw + (size_t)(nt*128 + lrow) * ldb;
    int asz = avalid ? 16 : 0;

    // swizzled smem offsets for this thread's 4 chunks (same for A and B tiles)
    uint32_t soff[4];
    #pragma unroll
    for (int i = 0; i < 4; i++){
        int c = lc0 + i;
        soff[i] = (uint32_t)(lrow*128 + ((c ^ (lrow & 7)) * 16));
    }

    auto stg_A = [&](int it, uint32_t buf){
        const char* ag = (const char*)(asrc + it*64);
        #pragma unroll
        for (int i = 0; i < 4; i++)
            cp16_(sbase + buf*32768u + soff[i], ag + (lc0+i)*16, asz);
    };

    float4 breg[8];
    auto ldg_B = [&](int it){
        const float4* bg = (const float4*)(bsrc + it*64 + lc0*8);
        #pragma unroll
        for (int i = 0; i < 8; i++) breg[i] = bg[i];
    };
    auto sts_B = [&](uint32_t buf){
        #pragma unroll
        for (int i = 0; i < 4; i++){
            __half2 h0 = __floats2half2_rn(breg[2*i].x,   breg[2*i].y);
            __half2 h1 = __floats2half2_rn(breg[2*i].z,   breg[2*i].w);
            __half2 h2 = __floats2half2_rn(breg[2*i+1].x, breg[2*i+1].y);
            __half2 h3 = __floats2half2_rn(breg[2*i+1].z, breg[2*i+1].w);
            uint4 pk;
            pk.x = *reinterpret_cast<uint32_t*>(&h0);
            pk.y = *reinterpret_cast<uint32_t*>(&h1);
            pk.z = *reinterpret_cast<uint32_t*>(&h2);
            pk.w = *reinterpret_cast<uint32_t*>(&h3);
            asm volatile("st.shared.v4.b32 [%0], {%1,%2,%3,%4};"
                :: "r"(sbase + buf*32768u + 16384u + soff[i]),
                   "r"(pk.x), "r"(pk.y), "r"(pk.z), "r"(pk.w) : "memory");
        }
    };

    float acc[2][8][4];
    #pragma unroll
    for (int i=0;i<2;i++)
        #pragma unroll
        for (int j=0;j<8;j++)
            #pragma unroll
            for (int k=0;k<4;k++) acc[i][j][k]=0.f;

    // ldmatrix lane pieces
    int a_rlo = (lane & 15);
    int a_chk = (lane >> 4);
    int b_rlo = (lane & 7) + ((lane & 16) ? 8 : 0);
    int b_chk = (lane >> 3) & 1;

    // prologue: stage 0 fully resident
    ldg_B(0);
    stg_A(0, 0);
    CP_COMMIT();
    sts_B(0);
    CP_WAIT0();
    __syncthreads();

    uint32_t cur = 0;
    for (int it = 0; it < NITER; it++){
        bool more = (it + 1 < NITER);
        if (more){
            ldg_B(it + 1);              // latency hidden under MMA below
            stg_A(it + 1, cur ^ 1u);
            CP_COMMIT();
        }

        uint32_t abase = sbase + cur*32768u;
        uint32_t bbase = abase + 16384u;
        #pragma unroll
        for (int ks = 0; ks < 4; ks++){
            uint32_t a[2][4];
            #pragma unroll
            for (int mtile = 0; mtile < 2; mtile++){
                int row = warp_m*32 + mtile*16 + a_rlo;
                int chunk = 2*ks + a_chk;
                uint32_t addr = abase + row*128 + ((chunk ^ (row & 7)) * 16);
                LDSM_X4(a[mtile][0], a[mtile][1], a[mtile][2], a[mtile][3], addr);
            }
            uint32_t b[8][2];
            #pragma unroll
            for (int n2 = 0; n2 < 4; n2++){
                int row = warp_n*64 + n2*16 + b_rlo;
                int chunk = 2*ks + b_chk;
                uint32_t addr = bbase + row*128 + ((chunk ^ (row & 7)) * 16);
                uint32_t r0,r1,r2,r3;
                LDSM_X4(r0, r1, r2, r3, addr);
                b[2*n2][0]=r0; b[2*n2][1]=r1;
                b[2*n2+1][0]=r2; b[2*n2+1][1]=r3;
            }
            #pragma unroll
            for (int mtile = 0; mtile < 2; mtile++)
                #pragma unroll
                for (int n8 = 0; n8 < 8; n8++)
                    MMA16816(acc[mtile][n8], a[mtile], b[n8]);
        }

        if (more) sts_B(cur ^ 1u);
        CP_WAIT0();
        __syncthreads();
        cur ^= 1u;
    }

    // ---- epilogue ----
    int m0 = mt*128 + warp_m*32;
    int n0 = nt*128 + warp_n*64;
    int gq = lane >> 2, tq = lane & 3;
    #pragma unroll
    for (int mtile = 0; mtile < 2; mtile++){
        int r_lo = m0 + mtile*16 + gq;
        int r_hi = r_lo + 8;
        if (EPI == EPI_DOWN){
            int tok_lo = g_rowtok[r_lo], tok_hi = g_rowtok[r_hi];
            float gl = g_rowgate[r_lo], gh = g_rowgate[r_hi];
            #pragma unroll
            for (int n8 = 0; n8 < 8; n8++){
                int col = n0 + n8*8 + tq*2;
                if (tok_lo >= 0){
                    size_t o = (size_t)tok_lo*ldc + col;
                    atomicAdd(&C[o],   gl*acc[mtile][n8][0]);
                    atomicAdd(&C[o+1], gl*acc[mtile][n8][1]);
                }
                if (tok_hi >= 0){
                    size_t o = (size_t)tok_hi*ldc + col;
                    atomicAdd(&C[o],   gh*acc[mtile][n8][2]);
                    atomicAdd(&C[o+1], gh*acc[mtile][n8][3]);
                }
            }
        } else if (EPI == EPI_RESID){
            #pragma unroll
            for (int n8 = 0; n8 < 8; n8++){
                int col = n0 + n8*8 + tq*2;
                size_t o_lo = (size_t)r_lo*ldc + col;
                size_t o_hi = (size_t)r_hi*ldc + col;
                float2 rv0 = *(const float2*)(resid + o_lo);
                float2 rv1 = *(const float2*)(resid + o_hi);
                float2 v0, v1;
                v0.x = acc[mtile][n8][0] + rv0.x;
                v0.y = acc[mtile][n8][1] + rv0.y;
                v1.x = acc[mtile][n8][2] + rv1.x;
                v1.y = acc[mtile][n8][3] + rv1.y;
                *(float2*)(C + o_lo) = v0;
                *(float2*)(C + o_hi) = v1;
                *(float2*)(Cdual + o_lo) = v0;
                *(float2*)(Cdual + o_hi) = v1;
            }
        } else {
            #pragma unroll
            for (int n8 = 0; n8 < 8; n8++){
                int col = n0 + n8*8 + tq*2;
                float2 v0, v1;
                v0.x = acc[mtile][n8][0]; v0.y = acc[mtile][n8][1];
                v1.x = acc[mtile][n8][2]; v1.y = acc[mtile][n8][3];
                *(float2*)(C + (size_t)r_lo*ldc + col) = v0;
                *(float2*)(C + (size_t)r_hi*ldc + col) = v1;
            }
        }
    }
}

// ============================ RoPE / attention ===============================
__global__ void k_rope(float* __restrict__ q) {
    int idx = blockIdx.x*blockDim.x + threadIdx.x;
    if (idx >= Tn*NHn*32) return;
    int i = idx & 31;
    int t = idx >> 9;
    int h = (idx >> 5) & (NHn-1);
    int s = t & (Sn-1);
    float invf = powf(10000.f, -((float)(2*i)) * (1.f/(float)HDn));
    float fr = (float)s * invf;
    float c, sn;
    sincosf(fr, &sn, &c);
    float* p = q + (size_t)t*Dn + h*HDn + i;
    float v1 = p[0], v2 = p[32];
    p[0]  = v1*c - v2*sn;
    p[32] = v2*c + v1*sn;
}

__global__ __launch_bounds__(256)
void k_attn(const float* __restrict__ Q, const float* __restrict__ Kg,
            const float* __restrict__ V, __half* __restrict__ O)
{
    __shared__ float Qs [64*64];
    __shared__ float KVs[64*64];
    __shared__ float Ps [64*64];
    int bh = blockIdx.x;
    int qt = blockIdx.y;
    int b = bh >> 4, h = bh & 15;
    int tid = threadIdx.x;
    int ty = tid >> 4, tx = tid & 15;
    size_t base = ((size_t)b*Sn)*Dn + (size_t)h*HDn;
    int q0 = qt*64;
    #pragma unroll
    for (int rep=0;rep<4;rep++){
        int lin = tid + rep*256;
        int r = lin >> 4, c = (lin & 15)*4;
        *(float4*)&Qs[r*64+c] = *(const float4*)(Q + base + (size_t)(q0+r)*Dn + c);
    }
    float acc[4][4];
    float mrow[4], lrow[4];
    #pragma unroll
    for (int i=0;i<4;i++){
        mrow[i] = -1e30f; lrow[i] = 0.f;
        #pragma unroll
        for (int j=0;j<4;j++) acc[i][j]=0.f;
    }
    __syncthreads();
    for (int kt=0; kt<=qt; kt++){
        int k0 = kt*64;
        #pragma unroll
        for (int rep=0;rep<4;rep++){
            int lin = tid + rep*256;
            int r = lin >> 4, c = (lin & 15)*4;
            float4 kv = *(const float4*)(Kg + base + (size_t)(k0+r)*Dn + c);
            KVs[(c+0)*64 + r] = kv.x;
            KVs[(c+1)*64 + r] = kv.y;
            KVs[(c+2)*64 + r] = kv.z;
            KVs[(c+3)*64 + r] = kv.w;
        }
        __syncthreads();
        float s[4][4];
        #pragma unroll
        for (int i=0;i<4;i++)
            #pragma unroll
            for (int j=0;j<4;j++) s[i][j]=0.f;
        #pragma unroll 4
        for (int d=0; d<64; d++){
            float qa[4], kb[4];
            #pragma unroll
            for (int i=0;i<4;i++) qa[i] = Qs[(ty*4+i)*64 + d];
            #pragma unroll
            for (int j=0;j<4;j++) kb[j] = KVs[d*64 + tx*4 + j];
            #pragma unroll
            for (int i=0;i<4;i++)
                #pragma unroll
                for (int j=0;j<4;j++) s[i][j] = fmaf(qa[i], kb[j], s[i][j]);
        }
        #pragma unroll
        for (int i=0;i<4;i++){
            int qq = q0 + ty*4 + i;
            #pragma unroll
            for (int j=0;j<4;j++){
                int kk = k0 + tx*4 + j;
                s[i][j] = (kk <= qq) ? s[i][j]*0.125f : -1e30f;
            }
        }
        #pragma unroll
        for (int i=0;i<4;i++){
            float mt = fmaxf(fmaxf(s[i][0],s[i][1]), fmaxf(s[i][2],s[i][3]));
            #pragma unroll
            for (int o=8;o;o>>=1) mt = fmaxf(mt, __shfl_xor_sync(0xffffffffu, mt, o));
            float mn = fmaxf(mrow[i], mt);
            float corr = __expf(mrow[i] - mn);
            float rs = 0.f;
            #pragma unroll
            for (int j=0;j<4;j++){ float p = __expf(s[i][j]-mn); s[i][j]=p; rs+=p; }
            #pragma unroll
            for (int o=8;o;o>>=1) rs += __shfl_xor_sync(0xffffffffu, rs, o);
            lrow[i] = lrow[i]*corr + rs;
            mrow[i] = mn;
            #pragma unroll
            for (int j=0;j<4;j++) acc[i][j] *= corr;
            #pragma unroll
            for (int j=0;j<4;j++) Ps[(ty*4+i)*64 + tx*4+j] = s[i][j];
        }
        __syncthreads();
        #pragma unroll
        for (int rep=0;rep<4;rep++){
            int lin = tid + rep*256;
            int r = lin >> 4, c = (lin & 15)*4;
            *(float4*)&KVs[r*64+c] = *(const float4*)(V + base + (size_t)(k0+r)*Dn + c);
        }
        __syncthreads();
        #pragma unroll 4
        for (int kv=0; kv<64; kv++){
            float pv[4], vv[4];
            #pragma unroll
            for (int i=0;i<4;i++) pv[i] = Ps[(ty*4+i)*64 + kv];
            #pragma unroll
            for (int j=0;j<4;j++) vv[j] = KVs[kv*64 + tx*4 + j];
            #pragma unroll
            for (int i=0;i<4;i++)
                #pragma unroll
                for (int j=0;j<4;j++) acc[i][j] = fmaf(pv[i], vv[j], acc[i][j]);
        }
        __syncthreads();
    }
    #pragma unroll
    for (int i=0;i<4;i++){
        float inv = 1.f/lrow[i];
        size_t o = base + (size_t)(q0+ty*4+i)*Dn + tx*4;
        __half2 p0 = __floats2half2_rn(acc[i][0]*inv, acc[i][1]*inv);
        __half2 p1 = __floats2half2_rn(acc[i][2]*inv, acc[i][3]*inv);
        *(__half2*)(O + o)     = p0;
        *(__half2*)(O + o + 2) = p1;
    }
}

// =============================== gating / MoE ================================
__global__ void k_gate(const float* __restrict__ xn, const float* __restrict__ gw)
{
    int t = blockIdx.x;
    int w = threadIdx.x >> 5, lane = threadIdx.x & 31;
    const float* xr = xn + (size_t)t * Dn;
    const float* gr = gw + (size_t)w * Dn;
    float acc = 0.f;
    for (int d = lane; d < Dn; d += 32) acc = fmaf(xr[d], gr[d], acc);
    #pragma unroll
    for (int o=16;o;o>>=1) acc += __shfl_xor_sync(0xffffffffu, acc, o);
    __shared__ float lg[En];
    if (lane == 0) lg[w] = acc;
    __syncthreads();
    if (threadIdx.x == 0){
        int i1 = 0;
        for (int e=1;e<En;e++) if (lg[e] > lg[i1]) i1 = e;
        int i2 = -1;
        for (int e=0;e<En;e++){
            if (e == i1) continue;
            if (i2 < 0 || lg[e] > lg[i2]) i2 = e;
        }
        float l1 = lg[i1], l2 = lg[i2];
        float e2 = expf(l2 - l1);
        float inv = 1.f/(1.f + e2);
        float gv1 = inv, gv2 = e2*inv;
        g_expid[t*2]   = i1; g_expid[t*2+1]   = i2;
        g_gateval[t*2] = gv1; g_gateval[t*2+1] = gv2;
        atomicAdd(&g_cnt[i1], 1); atomicAdd(&g_cnt[i2], 1);
        atomicAdd(&g_gsum[i1], gv1); atomicAdd(&g_gsum[i2], gv2);
        float mx = lg[0];
        for (int e=1;e<En;e++) mx = fmaxf(mx, lg[e]);
        float pe[En]; float se = 0.f;
        for (int e=0;e<En;e++){ pe[e] = expf(lg[e]-mx); se += pe[e]; }
        float pinv = 1.f/se;
        for (int e=0;e<En;e++) atomicAdd(&g_psum[e], pe[e]*pinv);
    }
}

__global__ void k_offsets(float* __restrict__ out, int write_aux)
{
    __shared__ int soff[En+1];
    if (threadIdx.x == 0){
        int tot = 0;
        for (int e=0;e<En;e++){
            soff[e] = tot;
            g_cursor[e] = tot;
            tot += ((g_cnt[e] + 127) >> 7) << 7;
        }
        soff[En] = tot;
        g_totalrows = tot;
        if (write_aux){
            float sacc = 0.f;
            for (int e=0;e<En;e++) sacc += g_gsum[e]*g_psum[e];
            out[(size_t)Tn*Dn] = (float)En * sacc / ((float)Tn*(float)Tn);
        }
    }
    __syncthreads();
    int tot = soff[En];
    for (int r = threadIdx.x; r < tot; r += blockDim.x){
        int e = 0;
        while (e+1 < En && r >= soff[e+1]) e++;
        g_rowexp[r] = e;
        g_rowtok[r] = -1;
    }
}

__global__ void k_scatter()
{
    int t = blockIdx.x*blockDim.x + threadIdx.x;
    if (t >= Tn) return;
    #pragma unroll
    for (int k=0;k<2;k++){
        int e = g_expid[t*2+k];
        int pos = atomicAdd(&g_cursor[e], 1);
        g_rowtok[pos] = t;
        g_rowgate[pos] = g_gateval[t*2+k];
    }
}

// H = silu(G) * U  -> fp16 Hh
__global__ void k_silumul()
{
    size_t i4 = ((size_t)blockIdx.x*blockDim.x + threadIdx.x) * 4;
    size_t n = (size_t)g_totalrows * HIDn;
    if (i4 >= n) return;
    float4 g = *(float4*)&g_GBUF[i4];
    float4 u = *(float4*)&g_UBUF[i4];
    float a = (g.x / (1.f + __expf(-g.x))) * u.x;
    float b = (g.y / (1.f + __expf(-g.y))) * u.y;
    float c = (g.z / (1.f + __expf(-g.z))) * u.z;
    float d = (g.w / (1.f + __expf(-g.w))) * u.w;
    __half2 h0 = __floats2half2_rn(a, b);
    __half2 h1 = __floats2half2_rn(c, d);
    uint2 o;
    o.x = *reinterpret_cast<uint32_t*>(&h0);
    o.y = *reinterpret_cast<uint32_t*>(&h1);
    *(uint2*)&g_Hh[i4] = o;
}

// ---------------------------------------------------------------------------
extern "C" void kernel_launch(void* const* d_in, const int* in_sizes, int n_in,
                              void* d_out, int out_size)
{
    (void)in_sizes; (void)n_in;
    const float* x   = (const float*)d_in[0];
    const float* wq  = (const float*)d_in[1];
    const float* wk  = (const float*)d_in[2];
    const float* wv  = (const float*)d_in[3];
    const float* wo  = (const float*)d_in[4];
    const float* anw = (const float*)d_in[5];
    const float* fnw = (const float*)d_in[6];
    const float* gw  = (const float*)d_in[7];
    const float* wge = (const float*)d_in[8];
    const float* wue = (const float*)d_in[9];
    const float* wde = (const float*)d_in[10];
    float* out = (float*)d_out;

    float *pQ,*pK,*pV,*pH,*pXN2,*pG,*pU;
    __half *pXNh,*pATTh,*pXN2h,*pHh;
    cudaGetSymbolAddress((void**)&pQ,    g_Qb);
    cudaGetSymbolAddress((void**)&pK,    g_Kb);
    cudaGetSymbolAddress((void**)&pV,    g_Vb);
    cudaGetSymbolAddress((void**)&pH,    g_Hb);
    cudaGetSymbolAddress((void**)&pXN2,  g_XN2);
    cudaGetSymbolAddress((void**)&pG,    g_GBUF);
    cudaGetSymbolAddress((void**)&pU,    g_UBUF);
    cudaGetSymbolAddress((void**)&pXNh,  g_XNh);
    cudaGetSymbolAddress((void**)&pATTh, g_ATTh);
    cudaGetSymbolAddress((void**)&pXN2h, g_XN2h);
    cudaGetSymbolAddress((void**)&pHh,   g_Hh);

    cudaFuncSetAttribute(k_gemm<16,EPI_PLAIN,false,false>,
                         cudaFuncAttributeMaxDynamicSharedMemorySize, GEMM_SMEM);
    cudaFuncSetAttribute(k_gemm<16,EPI_RESID,false,false>,
                         cudaFuncAttributeMaxDynamicSharedMemorySize, GEMM_SMEM);
    cudaFuncSetAttribute(k_gemm<16,EPI_PLAIN,true,true>,
                         cudaFuncAttributeMaxDynamicSharedMemorySize, GEMM_SMEM);
    cudaFuncSetAttribute(k_gemm<64,EPI_DOWN,false,true>,
                         cudaFuncAttributeMaxDynamicSharedMemorySize, GEMM_SMEM);

    k_reset<<<1, 32>>>();

    // attn pre-norm (fp16 only)
    k_rmsnorm<<<Tn, 256>>>(x, anw, nullptr, pXNh);

    // QKV projections (one launch, z selects weight/output); B = fp32 weights
    k_gemm<16,EPI_PLAIN,false,false><<<dim3(8,16,3), 256, GEMM_SMEM>>>(
        pXNh, Dn, wq, wk, wv, 0, Dn, pQ, pK, pV, Dn, nullptr, nullptr);

    // RoPE
    int nrope = Tn*NHn*32;
    k_rope<<<nrope/256, 256>>>(pQ);
    k_rope<<<nrope/256, 256>>>(pK);

    // attention (fp32 compute, fp16 output)
    k_attn<<<dim3(Bn*NHn, Sn/64), 256>>>(pQ, pK, pV, pATTh);

    // out proj + residual (writes H and d_out)
    k_gemm<16,EPI_RESID,false,false><<<dim3(8,16,1), 256, GEMM_SMEM>>>(
        pATTh, Dn, wo, wo, wo, 0, Dn, pH, pH, pH, Dn, x, out);

    // ffn pre-norm (fp32 for gating + fp16 for GEMMs)
    k_rmsnorm<<<Tn, 256>>>(pH, fnw, pXN2, pXN2h);

    // gating + routing
    k_gate<<<Tn, 256>>>(pXN2, gw);
    int write_aux = (out_size > Tn*Dn) ? 1 : 0;
    k_offsets<<<1, 256>>>(out, write_aux);
    k_scatter<<<(Tn+255)/256, 256>>>();

    // expert gate/up GEMMs (gathered rows; z selects gate vs up)
    k_gemm<16,EPI_PLAIN,true,true><<<dim3(32, MAXROWS/128, 2), 256, GEMM_SMEM>>>(
        pXN2h, Dn, wge, wue, wue, (long)HIDn*Dn, Dn, pG, pU, pU, HIDn,
        nullptr, nullptr);

    // SwiGLU elementwise -> fp16
    k_silumul<<<(MAXROWS*(HIDn/4))/256, 256>>>();

    // down GEMM + gated scatter-add into out
    k_gemm<64,EPI_DOWN,false,true><<<dim3(8, MAXROWS/128, 1), 256, GEMM_SMEM>>>(
        pHh, HIDn, wde, wde, wde, (long)Dn*HIDn, HIDn, out, out, out, Dn,
        nullptr, nullptr);
}